// round 13
// baseline (speedup 1.0000x reference)
#include <cuda_runtime.h>
#include <cuda_bf16.h>

#define FEAT 128
#define NMAX 131072
#define FULLMASK 0xffffffffu

// ---- device scratch (no allocations allowed) ----
__device__ int   g_cnt[NMAX];
__device__ float g_u[NMAX];     // u_j = sum_{e: src=j} 1/cnt[dst_e]
__device__ float g_v[NMAX];     // v_j = sum_{e: src=j} u[dst_e]/max(cnt[dst_e],1)
__device__ float g_meanx[FEAT]; // column sums of x (divide by N later)
__device__ float g_B[FEAT];     // B = sum_j u_j x_j
__device__ float g_A[FEAT];     // A = sum_j v_j x_j
__device__ float g_Sw;
__device__ int   g_is64;

// ---------------------------------------------------------------------------
// K0: zero scratch + detect int64 vs int32 edge_index.
// ---------------------------------------------------------------------------
__global__ void k_init(const void* __restrict__ edge, int N) {
    int i = blockIdx.x * blockDim.x + threadIdx.x;
    if (i < N) { g_cnt[i] = 0; g_u[i] = 0.f; g_v[i] = 0.f; }
    if (blockIdx.x == 0) {
        if (threadIdx.x < FEAT) {
            g_meanx[threadIdx.x] = 0.f;
            g_B[threadIdx.x] = 0.f;
            g_A[threadIdx.x] = 0.f;
        }
        if (threadIdx.x == 0) {
            g_Sw = 0.f;
            const int* w = (const int*)edge;
            int is64 = 1;
            #pragma unroll 1
            for (int k = 0; k < 64; k++) {
                if (w[2 * k + 1] != 0) { is64 = 0; break; }
            }
            g_is64 = is64;
        }
    }
}

// ---------------------------------------------------------------------------
// K1 (fused, proven): in-degree count atomics  +  column sums of x.
// Atomic part is latency-bound (idle DRAM); colsum part is DRAM-bound
// (idle latency slots) — they overlap inside each SM.
// ---------------------------------------------------------------------------
__global__ void k_count_colsum(const void* __restrict__ edge,
                               const float* __restrict__ x, int E, int N) {
    const int is64 = g_is64;
    const int nt = gridDim.x * blockDim.x;
    const int tid = blockIdx.x * blockDim.x + threadIdx.x;

    // --- part 1: cnt[dst]++ per edge ---
    if (is64) {
        const long long* dst = (const long long*)edge + E;
        for (int e = tid; e < E; e += nt) atomicAdd(&g_cnt[(int)dst[e]], 1);
    } else {
        const int* dst = (const int*)edge + E;
        for (int e = tid; e < E; e += nt) atomicAdd(&g_cnt[dst[e]], 1);
    }

    // --- part 2: column sums of x (warp-per-row, float4 lanes) ---
    const int lane = threadIdx.x & 31;
    const int warp = tid >> 5;
    const int nwarps = nt >> 5;
    float4 a = make_float4(0.f, 0.f, 0.f, 0.f);
    for (int r = warp; r < N; r += nwarps) {
        float4 xv = *(const float4*)(x + (long long)r * FEAT + lane * 4);
        a.x += xv.x; a.y += xv.y; a.z += xv.z; a.w += xv.w;
    }
    __shared__ float smx[FEAT];
    if (threadIdx.x < FEAT) smx[threadIdx.x] = 0.f;
    __syncthreads();
    int c = lane * 4;
    atomicAdd(&smx[c + 0], a.x); atomicAdd(&smx[c + 1], a.y);
    atomicAdd(&smx[c + 2], a.z); atomicAdd(&smx[c + 3], a.w);
    __syncthreads();
    if (threadIdx.x < FEAT) atomicAdd(&g_meanx[threadIdx.x], smx[threadIdx.x]);
}

// ---------------------------------------------------------------------------
// K2 (proven): u[src] += 1/max(cnt[dst],1).
// ---------------------------------------------------------------------------
__global__ void k_u(const void* __restrict__ edge, int E) {
    const int is64 = g_is64;
    const int nt = gridDim.x * blockDim.x;
    const long long* e64 = (const long long*)edge;
    const int* e32 = (const int*)edge;
    if (is64) {
        for (int e = blockIdx.x * blockDim.x + threadIdx.x; e < E; e += nt) {
            int s = (int)e64[e];
            int d = (int)e64[(long long)E + e];
            int cd = __ldg(&g_cnt[d]);
            atomicAdd(&g_u[s], 1.0f / (float)max(cd, 1));
        }
    } else {
        for (int e = blockIdx.x * blockDim.x + threadIdx.x; e < E; e += nt) {
            int s = e32[e];
            int d = e32[E + e];
            int cd = __ldg(&g_cnt[d]);
            atomicAdd(&g_u[s], 1.0f / (float)max(cd, 1));
        }
    }
}

// ---------------------------------------------------------------------------
// K3 (fused): v[src] += u[dst]/max(cnt[dst],1)  (t inlined, k_t eliminated)
//             OVERLAPPED WITH  B = sum_j u_j x_j (streaming; u is final).
// Same atomics+streaming overlap shape as K1.
// ---------------------------------------------------------------------------
__global__ void k_vB(const void* __restrict__ edge,
                     const float* __restrict__ x, int E, int N) {
    const int is64 = g_is64;
    const int nt = gridDim.x * blockDim.x;
    const int tid = blockIdx.x * blockDim.x + threadIdx.x;
    const long long* e64 = (const long long*)edge;
    const int* e32 = (const int*)edge;

    // --- part 1: v scatter with inline t ---
    if (is64) {
        for (int e = tid; e < E; e += nt) {
            int s = (int)e64[e];
            int d = (int)e64[(long long)E + e];
            float ud = __ldg(&g_u[d]);
            int cd = __ldg(&g_cnt[d]);
            atomicAdd(&g_v[s], ud / (float)max(cd, 1));
        }
    } else {
        for (int e = tid; e < E; e += nt) {
            int s = e32[e];
            int d = e32[E + e];
            float ud = __ldg(&g_u[d]);
            int cd = __ldg(&g_cnt[d]);
            atomicAdd(&g_v[s], ud / (float)max(cd, 1));
        }
    }

    // --- part 2: B = sum_j u_j x_j (warp-per-row streaming) ---
    const int lane = threadIdx.x & 31;
    const int warp = tid >> 5;
    const int nwarps = nt >> 5;
    float4 aB = make_float4(0.f, 0.f, 0.f, 0.f);
    for (int r = warp; r < N; r += nwarps) {
        float uj = __ldg(&g_u[r]);
        float4 xv = *(const float4*)(x + (long long)r * FEAT + lane * 4);
        aB.x = fmaf(uj, xv.x, aB.x); aB.y = fmaf(uj, xv.y, aB.y);
        aB.z = fmaf(uj, xv.z, aB.z); aB.w = fmaf(uj, xv.w, aB.w);
    }
    __shared__ float sB[FEAT];
    if (threadIdx.x < FEAT) sB[threadIdx.x] = 0.f;
    __syncthreads();
    int c = lane * 4;
    atomicAdd(&sB[c + 0], aB.x); atomicAdd(&sB[c + 1], aB.y);
    atomicAdd(&sB[c + 2], aB.z); atomicAdd(&sB[c + 3], aB.w);
    __syncthreads();
    if (threadIdx.x < FEAT) atomicAdd(&g_B[threadIdx.x], sB[threadIdx.x]);
}

// ---------------------------------------------------------------------------
// K4: A = sum_j v_j x_j (x L2-warm)  +  Sw = #nodes with cnt>0.
// Every row visited by exactly one warp; all lanes hold identical nz.
// ---------------------------------------------------------------------------
__global__ void k_a(const float* __restrict__ x, int N) {
    const int lane = threadIdx.x & 31;
    const int warp = (blockIdx.x * blockDim.x + threadIdx.x) >> 5;
    const int nwarps = (gridDim.x * blockDim.x) >> 5;

    float4 aA = make_float4(0.f, 0.f, 0.f, 0.f);
    int nz = 0;

    #pragma unroll 2
    for (int r = warp; r < N; r += nwarps) {
        float vj = __ldg(&g_v[r]);
        nz += (__ldg(&g_cnt[r]) > 0) ? 1 : 0;
        float4 xv = *(const float4*)(x + (long long)r * FEAT + lane * 4);
        aA.x = fmaf(vj, xv.x, aA.x); aA.y = fmaf(vj, xv.y, aA.y);
        aA.z = fmaf(vj, xv.z, aA.z); aA.w = fmaf(vj, xv.w, aA.w);
    }

    __shared__ float sA[FEAT];
    if (threadIdx.x < FEAT) sA[threadIdx.x] = 0.f;
    __syncthreads();
    int c = lane * 4;
    atomicAdd(&sA[c + 0], aA.x); atomicAdd(&sA[c + 1], aA.y);
    atomicAdd(&sA[c + 2], aA.z); atomicAdd(&sA[c + 3], aA.w);
    __syncthreads();
    if (threadIdx.x < FEAT) atomicAdd(&g_A[threadIdx.x], sA[threadIdx.x]);
    if (lane == 0 && nz > 0) atomicAdd(&g_Sw, (float)nz);
}

// ---------------------------------------------------------------------------
// K5: tiny final combine, single block of 128 threads.
//   mean_h1  = (B/N)@W1_l + (meanx/N)@W1_r + b1
//   v1       = A@W1_l + B@W1_r + Sw*b1 ;  mean_agg2 = v1/N
//   g        = mean_agg2@W2_l + mean_h1@W2_r + b2
//   out      = g@W_out + b_out
// ---------------------------------------------------------------------------
__global__ void k_final(const float* __restrict__ W1l, const float* __restrict__ W1r,
                        const float* __restrict__ b1,
                        const float* __restrict__ W2l, const float* __restrict__ W2r,
                        const float* __restrict__ b2,
                        const float* __restrict__ Wout, const float* __restrict__ bout,
                        float* __restrict__ out, int N, int C) {
    __shared__ float s_ma1[FEAT], s_mx[FEAT], s_A[FEAT], s_B[FEAT];
    __shared__ float s_mh1[FEAT], s_ma2[FEAT], s_g[FEAT];
    int t = threadIdx.x;
    float invN = 1.0f / (float)N;
    float Sw = g_Sw;
    s_B[t]  = g_B[t];
    s_A[t]  = g_A[t];
    s_ma1[t] = g_B[t] * invN;
    s_mx[t]  = g_meanx[t] * invN;
    __syncthreads();

    float mh = b1[t];
    float v1 = Sw * b1[t];
    #pragma unroll 8
    for (int k = 0; k < FEAT; k++) {
        float wl = W1l[k * FEAT + t];
        float wr = W1r[k * FEAT + t];
        mh = fmaf(s_ma1[k], wl, mh);
        mh = fmaf(s_mx[k],  wr, mh);
        v1 = fmaf(s_A[k],   wl, v1);
        v1 = fmaf(s_B[k],   wr, v1);
    }
    s_mh1[t] = mh;
    s_ma2[t] = v1 * invN;
    __syncthreads();

    float gv = b2[t];
    #pragma unroll 8
    for (int k = 0; k < FEAT; k++) {
        gv = fmaf(s_ma2[k], W2l[k * FEAT + t], gv);
        gv = fmaf(s_mh1[k], W2r[k * FEAT + t], gv);
    }
    s_g[t] = gv;
    __syncthreads();

    if (t < C) {
        float acc = bout[t];
        #pragma unroll 8
        for (int k = 0; k < FEAT; k++)
            acc = fmaf(s_g[k], Wout[k * C + t], acc);
        out[t] = acc;
    }
}

extern "C" void kernel_launch(void* const* d_in, const int* in_sizes, int n_in,
                              void* d_out, int out_size) {
    const float* x    = (const float*)d_in[0];
    const void*  edge = d_in[1];
    const float* W1l  = (const float*)d_in[2];
    const float* W1r  = (const float*)d_in[3];
    const float* b1   = (const float*)d_in[4];
    const float* W2l  = (const float*)d_in[5];
    const float* W2r  = (const float*)d_in[6];
    const float* b2   = (const float*)d_in[7];
    const float* Wout = (const float*)d_in[8];
    const float* bout = (const float*)d_in[9];
    float* out = (float*)d_out;

    int N = in_sizes[0] / FEAT;
    int E = in_sizes[1] / 2;
    int C = out_size;

    int nblk = (N + 255) / 256;
    k_init        <<<nblk, 256>>>(edge, N);
    k_count_colsum<<<1184, 256>>>(edge, x, E, N);
    k_u           <<<1184, 256>>>(edge, E);
    k_vB          <<<1184, 256>>>(edge, x, E, N);
    k_a           <<<1184, 256>>>(x, N);
    k_final<<<1, 128>>>(W1l, W1r, b1, W2l, W2r, b2, Wout, bout, out, N, C);
}

// round 14
// speedup vs baseline: 1.1453x; 1.1453x over previous
#include <cuda_runtime.h>
#include <cuda_bf16.h>

#define FEAT 128
#define NMAX 131072
#define FULLMASK 0xffffffffu

// ---- device scratch (no allocations allowed) ----
__device__ int   g_cnt[NMAX];
__device__ float g_u[NMAX];     // u_j = sum_{e: src=j} 1/cnt[dst_e]
__device__ float g_v[NMAX];     // v_j = sum_{e: src=j} u[dst_e]/max(cnt[dst_e],1)
__device__ float g_meanx[FEAT]; // column sums of x (divide by N later)
__device__ float g_B[FEAT];     // B = sum_j u_j x_j
__device__ float g_A[FEAT];     // A = sum_j v_j x_j
__device__ float g_Sw;
__device__ int   g_is64;

// ---------------------------------------------------------------------------
// K0: zero scratch + detect int64 vs int32 edge_index.
// ---------------------------------------------------------------------------
__global__ void k_init(const void* __restrict__ edge, int N) {
    int i = blockIdx.x * blockDim.x + threadIdx.x;
    if (i < N) { g_cnt[i] = 0; g_u[i] = 0.f; g_v[i] = 0.f; }
    if (blockIdx.x == 0) {
        if (threadIdx.x < FEAT) {
            g_meanx[threadIdx.x] = 0.f;
            g_B[threadIdx.x] = 0.f;
            g_A[threadIdx.x] = 0.f;
        }
        if (threadIdx.x == 0) {
            g_Sw = 0.f;
            const int* w = (const int*)edge;
            int is64 = 1;
            #pragma unroll 1
            for (int k = 0; k < 64; k++) {
                if (w[2 * k + 1] != 0) { is64 = 0; break; }
            }
            g_is64 = is64;
        }
    }
}

// ---------------------------------------------------------------------------
// K1 (fused, proven): in-degree count atomics  +  column sums of x.
// Atomic part is latency-bound (idle DRAM); colsum part is DRAM-bound
// (idle latency slots) — they overlap inside each SM.
// ---------------------------------------------------------------------------
__global__ void k_count_colsum(const void* __restrict__ edge,
                               const float* __restrict__ x, int E, int N) {
    const int is64 = g_is64;
    const int nt = gridDim.x * blockDim.x;
    const int tid = blockIdx.x * blockDim.x + threadIdx.x;

    // --- part 1: cnt[dst]++ per edge ---
    if (is64) {
        const long long* dst = (const long long*)edge + E;
        for (int e = tid; e < E; e += nt) atomicAdd(&g_cnt[(int)dst[e]], 1);
    } else {
        const int* dst = (const int*)edge + E;
        for (int e = tid; e < E; e += nt) atomicAdd(&g_cnt[dst[e]], 1);
    }

    // --- part 2: column sums of x (warp-per-row, float4 lanes) ---
    const int lane = threadIdx.x & 31;
    const int warp = tid >> 5;
    const int nwarps = nt >> 5;
    float4 a = make_float4(0.f, 0.f, 0.f, 0.f);
    for (int r = warp; r < N; r += nwarps) {
        float4 xv = *(const float4*)(x + (long long)r * FEAT + lane * 4);
        a.x += xv.x; a.y += xv.y; a.z += xv.z; a.w += xv.w;
    }
    __shared__ float smx[FEAT];
    if (threadIdx.x < FEAT) smx[threadIdx.x] = 0.f;
    __syncthreads();
    int c = lane * 4;
    atomicAdd(&smx[c + 0], a.x); atomicAdd(&smx[c + 1], a.y);
    atomicAdd(&smx[c + 2], a.z); atomicAdd(&smx[c + 3], a.w);
    __syncthreads();
    if (threadIdx.x < FEAT) atomicAdd(&g_meanx[threadIdx.x], smx[threadIdx.x]);
}

// ---------------------------------------------------------------------------
// K2 (proven): u[src] += 1/max(cnt[dst],1).
// ---------------------------------------------------------------------------
__global__ void k_u(const void* __restrict__ edge, int E) {
    const int is64 = g_is64;
    const int nt = gridDim.x * blockDim.x;
    const long long* e64 = (const long long*)edge;
    const int* e32 = (const int*)edge;
    for (int e = blockIdx.x * blockDim.x + threadIdx.x; e < E; e += nt) {
        int s, d;
        if (is64) { s = (int)e64[e]; d = (int)e64[(long long)E + e]; }
        else      { s = e32[e];      d = e32[E + e]; }
        int cd = __ldg(&g_cnt[d]);
        atomicAdd(&g_u[s], 1.0f / (float)max(cd, 1));
    }
}

// ---------------------------------------------------------------------------
// K3: v[src] += u[dst]/max(cnt[dst],1).  t inlined (k_t eliminated); both
// gathers are L2-hot 4B loads into separate dense arrays.  NO streaming
// fusion here (R13 showed it serializes against the scatter).
// ---------------------------------------------------------------------------
__global__ void k_v(const void* __restrict__ edge, int E) {
    const int is64 = g_is64;
    const int nt = gridDim.x * blockDim.x;
    const long long* e64 = (const long long*)edge;
    const int* e32 = (const int*)edge;
    for (int e = blockIdx.x * blockDim.x + threadIdx.x; e < E; e += nt) {
        int s, d;
        if (is64) { s = (int)e64[e]; d = (int)e64[(long long)E + e]; }
        else      { s = e32[e];      d = e32[E + e]; }
        float ud = __ldg(&g_u[d]);
        int   cd = __ldg(&g_cnt[d]);
        atomicAdd(&g_v[s], ud / (float)max(cd, 1));
    }
}

// ---------------------------------------------------------------------------
// K4: weighted pass over x (L2-hot after k_count_colsum):
//   B += u_j * x[j];  A += v_j * x[j];  Sw = #nodes with cnt>0.
// cnt read is lane-uniform (broadcast, ~free). Every row visited by exactly
// one warp; all lanes hold identical nz.
// ---------------------------------------------------------------------------
__global__ void k_ba(const float* __restrict__ x, int N) {
    const int lane = threadIdx.x & 31;
    const int warp = (blockIdx.x * blockDim.x + threadIdx.x) >> 5;
    const int nwarps = (gridDim.x * blockDim.x) >> 5;

    float4 aB = make_float4(0.f, 0.f, 0.f, 0.f);
    float4 aA = make_float4(0.f, 0.f, 0.f, 0.f);
    int nz = 0;

    #pragma unroll 2
    for (int r = warp; r < N; r += nwarps) {
        float uj = __ldg(&g_u[r]);
        float vj = __ldg(&g_v[r]);
        nz += (__ldg(&g_cnt[r]) > 0) ? 1 : 0;
        float4 xv = *(const float4*)(x + (long long)r * FEAT + lane * 4);
        aB.x = fmaf(uj, xv.x, aB.x); aB.y = fmaf(uj, xv.y, aB.y);
        aB.z = fmaf(uj, xv.z, aB.z); aB.w = fmaf(uj, xv.w, aB.w);
        aA.x = fmaf(vj, xv.x, aA.x); aA.y = fmaf(vj, xv.y, aA.y);
        aA.z = fmaf(vj, xv.z, aA.z); aA.w = fmaf(vj, xv.w, aA.w);
    }

    __shared__ float sB[FEAT], sA[FEAT];
    if (threadIdx.x < FEAT) { sB[threadIdx.x] = 0.f; sA[threadIdx.x] = 0.f; }
    __syncthreads();
    int c = lane * 4;
    atomicAdd(&sB[c + 0], aB.x); atomicAdd(&sB[c + 1], aB.y);
    atomicAdd(&sB[c + 2], aB.z); atomicAdd(&sB[c + 3], aB.w);
    atomicAdd(&sA[c + 0], aA.x); atomicAdd(&sA[c + 1], aA.y);
    atomicAdd(&sA[c + 2], aA.z); atomicAdd(&sA[c + 3], aA.w);
    __syncthreads();
    if (threadIdx.x < FEAT) {
        atomicAdd(&g_B[threadIdx.x], sB[threadIdx.x]);
        atomicAdd(&g_A[threadIdx.x], sA[threadIdx.x]);
    }
    if (lane == 0 && nz > 0) atomicAdd(&g_Sw, (float)nz);
}

// ---------------------------------------------------------------------------
// K5: tiny final combine, single block of 128 threads.
//   mean_h1  = (B/N)@W1_l + (meanx/N)@W1_r + b1
//   v1       = A@W1_l + B@W1_r + Sw*b1 ;  mean_agg2 = v1/N
//   g        = mean_agg2@W2_l + mean_h1@W2_r + b2
//   out      = g@W_out + b_out
// ---------------------------------------------------------------------------
__global__ void k_final(const float* __restrict__ W1l, const float* __restrict__ W1r,
                        const float* __restrict__ b1,
                        const float* __restrict__ W2l, const float* __restrict__ W2r,
                        const float* __restrict__ b2,
                        const float* __restrict__ Wout, const float* __restrict__ bout,
                        float* __restrict__ out, int N, int C) {
    __shared__ float s_ma1[FEAT], s_mx[FEAT], s_A[FEAT], s_B[FEAT];
    __shared__ float s_mh1[FEAT], s_ma2[FEAT], s_g[FEAT];
    int t = threadIdx.x;
    float invN = 1.0f / (float)N;
    float Sw = g_Sw;
    s_B[t]  = g_B[t];
    s_A[t]  = g_A[t];
    s_ma1[t] = g_B[t] * invN;
    s_mx[t]  = g_meanx[t] * invN;
    __syncthreads();

    float mh = b1[t];
    float v1 = Sw * b1[t];
    #pragma unroll 8
    for (int k = 0; k < FEAT; k++) {
        float wl = W1l[k * FEAT + t];
        float wr = W1r[k * FEAT + t];
        mh = fmaf(s_ma1[k], wl, mh);
        mh = fmaf(s_mx[k],  wr, mh);
        v1 = fmaf(s_A[k],   wl, v1);
        v1 = fmaf(s_B[k],   wr, v1);
    }
    s_mh1[t] = mh;
    s_ma2[t] = v1 * invN;
    __syncthreads();

    float gv = b2[t];
    #pragma unroll 8
    for (int k = 0; k < FEAT; k++) {
        gv = fmaf(s_ma2[k], W2l[k * FEAT + t], gv);
        gv = fmaf(s_mh1[k], W2r[k * FEAT + t], gv);
    }
    s_g[t] = gv;
    __syncthreads();

    if (t < C) {
        float acc = bout[t];
        #pragma unroll 8
        for (int k = 0; k < FEAT; k++)
            acc = fmaf(s_g[k], Wout[k * C + t], acc);
        out[t] = acc;
    }
}

extern "C" void kernel_launch(void* const* d_in, const int* in_sizes, int n_in,
                              void* d_out, int out_size) {
    const float* x    = (const float*)d_in[0];
    const void*  edge = d_in[1];
    const float* W1l  = (const float*)d_in[2];
    const float* W1r  = (const float*)d_in[3];
    const float* b1   = (const float*)d_in[4];
    const float* W2l  = (const float*)d_in[5];
    const float* W2r  = (const float*)d_in[6];
    const float* b2   = (const float*)d_in[7];
    const float* Wout = (const float*)d_in[8];
    const float* bout = (const float*)d_in[9];
    float* out = (float*)d_out;

    int N = in_sizes[0] / FEAT;
    int E = in_sizes[1] / 2;
    int C = out_size;

    int nblk = (N + 255) / 256;
    k_init        <<<nblk, 256>>>(edge, N);
    k_count_colsum<<<1184, 256>>>(edge, x, E, N);
    k_u           <<<1184, 256>>>(edge, E);
    k_v           <<<1184, 256>>>(edge, E);
    k_ba          <<<1184, 256>>>(x, N);
    k_final<<<1, 128>>>(W1l, W1r, b1, W2l, W2r, b2, Wout, bout, out, N, C);
}

// round 17
// speedup vs baseline: 1.2530x; 1.0941x over previous
#include <cuda_runtime.h>
#include <cuda_bf16.h>

#define FEAT 128
#define NMAX 131072
#define FULLMASK 0xffffffffu

// ---- device scratch (no allocations allowed) ----
__device__ int   g_cnt[NMAX];
__device__ float g_u[NMAX];     // u_j = sum_{e: src=j} 1/cnt[dst_e]
__device__ float g_t[NMAX];     // t_j = u_j / max(cnt_j,1)
__device__ float g_v[NMAX];     // v_j = sum_{e: src=j} t[dst_e]
__device__ float g_meanx[FEAT]; // column sums of x (divide by N later)
__device__ float g_B[FEAT];     // B = sum_j u_j x_j
__device__ float g_A[FEAT];     // A = sum_j v_j x_j
__device__ float g_Sw;
__device__ int   g_is64;

// ---------------------------------------------------------------------------
// K0: zero scratch + detect int64 vs int32 edge_index.  (Zero-at-entry:
// proven correct under graph replay; zero-at-exit failed validation in R15.)
// ---------------------------------------------------------------------------
__global__ void k_init(const void* __restrict__ edge, int N) {
    int i = blockIdx.x * blockDim.x + threadIdx.x;
    if (i < N) { g_cnt[i] = 0; g_u[i] = 0.f; g_v[i] = 0.f; }
    if (blockIdx.x == 0) {
        if (threadIdx.x < FEAT) {
            g_meanx[threadIdx.x] = 0.f;
            g_B[threadIdx.x] = 0.f;
            g_A[threadIdx.x] = 0.f;
        }
        if (threadIdx.x == 0) {
            g_Sw = 0.f;
            const int* w = (const int*)edge;
            int is64 = 1;
            #pragma unroll 1
            for (int k = 0; k < 64; k++) {
                if (w[2 * k + 1] != 0) { is64 = 0; break; }
            }
            g_is64 = is64;
        }
    }
}

// ---------------------------------------------------------------------------
// K1 (fused, proven): in-degree count atomics  +  column sums of x.
// Atomic part is latency-bound (idle DRAM); colsum part is DRAM-bound
// (idle latency slots) — they overlap inside each SM.
// ---------------------------------------------------------------------------
__global__ void k_count_colsum(const void* __restrict__ edge,
                               const float* __restrict__ x, int E, int N) {
    const int is64 = g_is64;
    const int nt = gridDim.x * blockDim.x;
    const int tid = blockIdx.x * blockDim.x + threadIdx.x;

    // --- part 1: cnt[dst]++ per edge ---
    if (is64) {
        const long long* dst = (const long long*)edge + E;
        for (int e = tid; e < E; e += nt) atomicAdd(&g_cnt[(int)dst[e]], 1);
    } else {
        const int* dst = (const int*)edge + E;
        for (int e = tid; e < E; e += nt) atomicAdd(&g_cnt[dst[e]], 1);
    }

    // --- part 2: column sums of x (warp-per-row, float4 lanes) ---
    const int lane = threadIdx.x & 31;
    const int warp = tid >> 5;
    const int nwarps = nt >> 5;
    float4 a = make_float4(0.f, 0.f, 0.f, 0.f);
    for (int r = warp; r < N; r += nwarps) {
        float4 xv = *(const float4*)(x + (long long)r * FEAT + lane * 4);
        a.x += xv.x; a.y += xv.y; a.z += xv.z; a.w += xv.w;
    }
    __shared__ float smx[FEAT];
    if (threadIdx.x < FEAT) smx[threadIdx.x] = 0.f;
    __syncthreads();
    int c = lane * 4;
    atomicAdd(&smx[c + 0], a.x); atomicAdd(&smx[c + 1], a.y);
    atomicAdd(&smx[c + 2], a.z); atomicAdd(&smx[c + 3], a.w);
    __syncthreads();
    if (threadIdx.x < FEAT) atomicAdd(&g_meanx[threadIdx.x], smx[threadIdx.x]);
}

// ---------------------------------------------------------------------------
// K2: u[src] += 1/max(cnt[dst],1).  __fdividef = MUFU.RCP path (short
// dependency chain; ~2e-7 rel error, tolerance is 1e-3).
// ---------------------------------------------------------------------------
__global__ void k_u(const void* __restrict__ edge, int E) {
    const int is64 = g_is64;
    const int nt = gridDim.x * blockDim.x;
    const long long* e64 = (const long long*)edge;
    const int* e32 = (const int*)edge;
    for (int e = blockIdx.x * blockDim.x + threadIdx.x; e < E; e += nt) {
        int s, d;
        if (is64) { s = (int)e64[e]; d = (int)e64[(long long)E + e]; }
        else      { s = e32[e];      d = e32[E + e]; }
        int cd = __ldg(&g_cnt[d]);
        atomicAdd(&g_u[s], __fdividef(1.0f, (float)max(cd, 1)));
    }
}

// ---------------------------------------------------------------------------
// K3: t = u/max(cnt,1);  Sw = #nodes with cnt>0.  Also warms u/cnt lines
// in L2 right before k_v's random gathers of t.
// ---------------------------------------------------------------------------
__global__ void k_t(int N) {
    int i = blockIdx.x * blockDim.x + threadIdx.x;
    int nz = 0;
    if (i < N) {
        int c = g_cnt[i];
        g_t[i] = __fdividef(g_u[i], (float)max(c, 1));
        nz = (c > 0) ? 1 : 0;
    }
    unsigned b = __ballot_sync(FULLMASK, nz);
    if ((threadIdx.x & 31) == 0 && b)
        atomicAdd(&g_Sw, (float)__popc(b));
}

// ---------------------------------------------------------------------------
// K4 (proven): v[src] += t[dst].
// ---------------------------------------------------------------------------
__global__ void k_v(const void* __restrict__ edge, int E) {
    const int is64 = g_is64;
    const int nt = gridDim.x * blockDim.x;
    const long long* e64 = (const long long*)edge;
    const int* e32 = (const int*)edge;
    for (int e = blockIdx.x * blockDim.x + threadIdx.x; e < E; e += nt) {
        int s, d;
        if (is64) { s = (int)e64[e]; d = (int)e64[(long long)E + e]; }
        else      { s = e32[e];      d = e32[E + e]; }
        atomicAdd(&g_v[s], __ldg(&g_t[d]));
    }
}

// ---------------------------------------------------------------------------
// K5 (proven): weighted pass over x (L2-hot after k_count_colsum):
//   B += u_j * x[j];  A += v_j * x[j]
// ---------------------------------------------------------------------------
__global__ void k_ba(const float* __restrict__ x, int N) {
    const int lane = threadIdx.x & 31;
    const int warp = (blockIdx.x * blockDim.x + threadIdx.x) >> 5;
    const int nwarps = (gridDim.x * blockDim.x) >> 5;

    float4 aB = make_float4(0.f, 0.f, 0.f, 0.f);
    float4 aA = make_float4(0.f, 0.f, 0.f, 0.f);

    #pragma unroll 2
    for (int r = warp; r < N; r += nwarps) {
        float uj = __ldg(&g_u[r]);
        float vj = __ldg(&g_v[r]);
        float4 xv = *(const float4*)(x + (long long)r * FEAT + lane * 4);
        aB.x = fmaf(uj, xv.x, aB.x); aB.y = fmaf(uj, xv.y, aB.y);
        aB.z = fmaf(uj, xv.z, aB.z); aB.w = fmaf(uj, xv.w, aB.w);
        aA.x = fmaf(vj, xv.x, aA.x); aA.y = fmaf(vj, xv.y, aA.y);
        aA.z = fmaf(vj, xv.z, aA.z); aA.w = fmaf(vj, xv.w, aA.w);
    }

    __shared__ float sB[FEAT], sA[FEAT];
    if (threadIdx.x < FEAT) { sB[threadIdx.x] = 0.f; sA[threadIdx.x] = 0.f; }
    __syncthreads();
    int c = lane * 4;
    atomicAdd(&sB[c + 0], aB.x); atomicAdd(&sB[c + 1], aB.y);
    atomicAdd(&sB[c + 2], aB.z); atomicAdd(&sB[c + 3], aB.w);
    atomicAdd(&sA[c + 0], aA.x); atomicAdd(&sA[c + 1], aA.y);
    atomicAdd(&sA[c + 2], aA.z); atomicAdd(&sA[c + 3], aA.w);
    __syncthreads();
    if (threadIdx.x < FEAT) {
        atomicAdd(&g_B[threadIdx.x], sB[threadIdx.x]);
        atomicAdd(&g_A[threadIdx.x], sA[threadIdx.x]);
    }
}

// ---------------------------------------------------------------------------
// K6: tiny final combine, single block of 128 threads.
//   mean_h1  = (B/N)@W1_l + (meanx/N)@W1_r + b1
//   v1       = A@W1_l + B@W1_r + Sw*b1 ;  mean_agg2 = v1/N
//   g        = mean_agg2@W2_l + mean_h1@W2_r + b2
//   out      = g@W_out + b_out
// ---------------------------------------------------------------------------
__global__ void k_final(const float* __restrict__ W1l, const float* __restrict__ W1r,
                        const float* __restrict__ b1,
                        const float* __restrict__ W2l, const float* __restrict__ W2r,
                        const float* __restrict__ b2,
                        const float* __restrict__ Wout, const float* __restrict__ bout,
                        float* __restrict__ out, int N, int C) {
    __shared__ float s_ma1[FEAT], s_mx[FEAT], s_A[FEAT], s_B[FEAT];
    __shared__ float s_mh1[FEAT], s_ma2[FEAT], s_g[FEAT];
    int t = threadIdx.x;
    float invN = 1.0f / (float)N;
    float Sw = g_Sw;
    s_B[t]  = g_B[t];
    s_A[t]  = g_A[t];
    s_ma1[t] = g_B[t] * invN;
    s_mx[t]  = g_meanx[t] * invN;
    __syncthreads();

    float mh = b1[t];
    float v1 = Sw * b1[t];
    #pragma unroll 8
    for (int k = 0; k < FEAT; k++) {
        float wl = W1l[k * FEAT + t];
        float wr = W1r[k * FEAT + t];
        mh = fmaf(s_ma1[k], wl, mh);
        mh = fmaf(s_mx[k],  wr, mh);
        v1 = fmaf(s_A[k],   wl, v1);
        v1 = fmaf(s_B[k],   wr, v1);
    }
    s_mh1[t] = mh;
    s_ma2[t] = v1 * invN;
    __syncthreads();

    float gv = b2[t];
    #pragma unroll 8
    for (int k = 0; k < FEAT; k++) {
        gv = fmaf(s_ma2[k], W2l[k * FEAT + t], gv);
        gv = fmaf(s_mh1[k], W2r[k * FEAT + t], gv);
    }
    s_g[t] = gv;
    __syncthreads();

    if (t < C) {
        float acc = bout[t];
        #pragma unroll 8
        for (int k = 0; k < FEAT; k++)
            acc = fmaf(s_g[k], Wout[k * C + t], acc);
        out[t] = acc;
    }
}

extern "C" void kernel_launch(void* const* d_in, const int* in_sizes, int n_in,
                              void* d_out, int out_size) {
    const float* x    = (const float*)d_in[0];
    const void*  edge = d_in[1];
    const float* W1l  = (const float*)d_in[2];
    const float* W1r  = (const float*)d_in[3];
    const float* b1   = (const float*)d_in[4];
    const float* W2l  = (const float*)d_in[5];
    const float* W2r  = (const float*)d_in[6];
    const float* b2   = (const float*)d_in[7];
    const float* Wout = (const float*)d_in[8];
    const float* bout = (const float*)d_in[9];
    float* out = (float*)d_out;

    int N = in_sizes[0] / FEAT;
    int E = in_sizes[1] / 2;
    int C = out_size;

    int nblk = (N + 255) / 256;
    k_init        <<<nblk, 256>>>(edge, N);
    k_count_colsum<<<1184, 256>>>(edge, x, E, N);
    k_u           <<<1184, 256>>>(edge, E);
    k_t           <<<nblk, 256>>>(N);
    k_v           <<<1184, 256>>>(edge, E);
    k_ba          <<<1184, 256>>>(x, N);
    k_final<<<1, 128>>>(W1l, W1r, b1, W2l, W2r, b2, Wout, bout, out, N, C);
}